// round 10
// baseline (speedup 1.0000x reference)
#include <cuda_runtime.h>

#define T_NO 200
#define SUB  16
#define E_NO 2000
#define I_NO 500
#define TD   20000
#define CB   16
#define NCH  2500          // TD/8 chunks

#define PADT 256
#define TDP  (TD + PADT)
#define CT2  2048          // t-span per conv block

// smem layout (floats) for k_scan
#define RING0 0            // 16 rows x 513
#define LUT0  8208         // 2 x 256 x 16
#define PART0 16400        // 16 warps x 288
#define HB0   21008        // 4 slots x 8 x 17
#define SMF   21552

__device__ float g_eT[SUB * TDP];     // pooled e counts, [s][PADT+t], pad=0
__device__ float g_iT[SUB * TDP];
__device__ float g_syn[TD * SUB];     // conv + Theta folded, [t][s]
__device__ int   g_asn_e[E_NO];
__device__ int   g_asn_i[I_NO];
__device__ float g_ek[SUB * T_NO];
__device__ float g_ik[SUB * T_NO];
__device__ float g_sk[SUB * T_NO];
__device__ float g_hk[SUB * T_NO];
__device__ float g_B[SUB * SUB];      // C_den * A_k * r_k  (IIR injection)
__device__ float g_spkc[3 * SUB];     // r, 2r, -r^2

__global__ void k_prep(const float* __restrict__ C_syn_e,
                       const float* __restrict__ C_syn_i,
                       const float* __restrict__ C_den,
                       const float* __restrict__ Te, const float* __restrict__ Ti,
                       const float* __restrict__ We, const float* __restrict__ Wi,
                       const float* __restrict__ De, const float* __restrict__ Di,
                       const float* __restrict__ Tspk, const float* __restrict__ Wspk,
                       const float* __restrict__ Whist,
                       float* __restrict__ out_filt)
{
    int tid = threadIdx.x;
    for (int e = tid; e < E_NO; e += blockDim.x) {
        int a = 0;
        for (int s = 0; s < SUB; s++)
            if (C_syn_e[s * E_NO + e] > 0.5f) a = s;
        g_asn_e[e] = a;
    }
    for (int i = tid; i < I_NO; i += blockDim.x) {
        int a = 0;
        for (int s = 0; s < SUB; s++)
            if (C_syn_i[s * I_NO + i] > 0.5f) a = s;
        g_asn_i[i] = a;
    }
    for (int s = tid; s < SUB; s += blockDim.x) {
        float r = expf(-1.0f / expf(Tspk[s]));
        g_spkc[s] = r; g_spkc[SUB + s] = 2.0f * r; g_spkc[2 * SUB + s] = -r * r;
    }
    for (int idx = tid; idx < SUB * SUB; idx += blockDim.x) {
        int k = idx & 15;
        float r = expf(-1.0f / expf(Tspk[k]));
        g_B[idx] = C_den[idx] * expf(Wspk[k] - Tspk[k]) * r;
    }
    const float PI = 3.14159265358979323846f;
    for (int idx = tid; idx < SUB * T_NO; idx += blockDim.x) {
        int s = idx / T_NO, tau = idx % T_NO;
        float t = (float)tau;
        float te  = fmaxf(t - expf(De[s]), 0.0f);
        float tte = te / expf(Te[s]);
        float ek  = tte * expf(-tte) * expf(We[s]);
        float ti_ = fmaxf(t - expf(Di[s]), 0.0f);
        float tti = ti_ / expf(Ti[s]);
        float ik  = -tti * expf(-tti) * expf(Wi[s]);
        float tts = t / expf(Tspk[s]);
        float sk  = tts * expf(-tts) * expf(Wspk[s]);
        float raw = 4.0f * logf(t + 1.0f);
        float hk  = 0.0f;
        for (int b = 0; b < CB; b++) {
            float phi = (PI * 0.5f) * (float)b;
            float v   = 0.5f * cosf(raw - phi) + 0.5f;
            if (raw < phi - PI || raw > phi + PI) v = 0.0f;
            hk += Whist[s * CB + b] * v;
        }
        g_ek[idx] = ek; g_ik[idx] = ik; g_sk[idx] = sk; g_hk[idx] = hk;
        out_filt[(s)      * T_NO + tau] = ek;
        out_filt[(16 + s) * T_NO + tau] = ik;
        out_filt[(32 + s) * T_NO + tau] = sk;
        out_filt[(48 + s) * T_NO + tau] = hk;
    }
}

__global__ void k_syn(const float* __restrict__ Se, const float* __restrict__ Si)
{
    __shared__ float be[SUB], bi[SUB];
    int t = blockIdx.x, tid = threadIdx.x;
    if (tid < SUB) { be[tid] = 0.0f; bi[tid] = 0.0f; }
    __syncthreads();
    for (int e = tid; e < E_NO; e += blockDim.x) {
        float v = Se[(size_t)t * E_NO + e];
        if (v != 0.0f) atomicAdd(&be[g_asn_e[e]], v);
    }
    for (int i = tid; i < I_NO; i += blockDim.x) {
        float v = Si[(size_t)t * I_NO + i];
        if (v != 0.0f) atomicAdd(&bi[g_asn_i[i]], v);
    }
    __syncthreads();
    if (tid < SUB) {
        g_eT[tid * TDP + PADT + t] = be[tid];
        g_iT[tid * TDP + PADT + t] = bi[tid];
    }
}

// conv: transposed smem-staged FIR (unchanged from R9)
__global__ void __launch_bounds__(256) k_conv(const float* __restrict__ Theta)
{
    __shared__ float se[2256], si[2256];
    __shared__ float ke[T_NO], ki[T_NO];
    int s = blockIdx.y;
    int tbase = blockIdx.x * CT2;
    int tid = threadIdx.x;

    for (int i = tid; i < T_NO; i += 256) {
        ke[i] = g_ek[s * T_NO + i];
        ki[i] = g_ik[s * T_NO + i];
    }
    const float* ge = &g_eT[s * TDP + PADT + tbase - 200];
    const float* gi = &g_iT[s * TDP + PADT + tbase - 200];
    int limit = TD - tbase + 200;
    for (int i = tid; i < 2256; i += 256) {
        bool ok = (i < limit);
        se[i] = ok ? __ldg(&ge[i]) : 0.0f;
        si[i] = ok ? __ldg(&gi[i]) : 0.0f;
    }
    __syncthreads();

    int t0 = tbase + tid * 8;
    if (t0 >= TD) return;
    float th = Theta[s];
    float acc[8];
    #pragma unroll
    for (int l = 0; l < 8; l++) acc[l] = th;

    int base = tid * 8;
    float we[8], wi[8];
    #pragma unroll
    for (int l = 0; l < 8; l++) { we[l] = se[base + l]; wi[l] = si[base + l]; }

    for (int jb = 0; jb < 25; jb++) {
        #pragma unroll
        for (int p = 0; p < 8; p++) {
            int j = jb * 8 + p;
            float ce = ke[199 - j], ci = ki[199 - j];
            #pragma unroll
            for (int l = 0; l < 8; l++) {
                acc[l] = fmaf(ce, we[(p + l) & 7], acc[l]);
                acc[l] = fmaf(ci, wi[(p + l) & 7], acc[l]);
            }
            we[p] = se[base + j + 8];
            wi[p] = si[base + j + 8];
        }
    }
    #pragma unroll
    for (int l = 0; l < 8; l++)
        if (t0 + l < TD) g_syn[(t0 + l) * SUB + s] = acc[l];
}

// chunked scan v3: chunk=8, ONE barrier/chunk.
//  wid 0  conductor: hist d=1..23 in regs (shift-free fb), spk = 2-state IIR
//         + mask-LUT injection (2-step slack).
//  wid 4  out-warp: writes chunk kc-1's spikes as 32x STG.128 from the ring.
//  16 helpers (SMSP-balanced wids): hist d=24..200 for chunk kc+2 (a full
//         chunk of latency slack), 6 consecutive taps/lane, transpose reduce,
//         4-slot rotating hbuf.
__global__ void __launch_bounds__(640, 1) k_scan(float* __restrict__ out)
{
    extern __shared__ float sm[];
    int tid = threadIdx.x, wid = tid >> 5, lane = tid & 31;

    for (int i = tid; i < SMF; i += blockDim.x) sm[i] = 0.0f;
    __syncthreads();
    for (int idx = tid; idx < 8192; idx += blockDim.x) {
        int m = (idx >> 4) & 255, s = idx & 15, h = idx >> 12;
        float v = 0.0f;
        #pragma unroll
        for (int b = 0; b < 8; b++)
            if ((m >> b) & 1) v += g_B[s * SUB + 8 * h + b];
        sm[LUT0 + idx] = v;
    }

    if (wid == 0) {
        // ------------- conductor -------------
        int s = lane & 15;
        float hkr[23];
        #pragma unroll
        for (int i = 0; i < 23; i++) hkr[i] = g_hk[s * T_NO + i];
        float twor = g_spkc[SUB + s], nr2 = g_spkc[2 * SUB + s];
        float carry[23];
        #pragma unroll
        for (int i = 0; i < 23; i++) carry[i] = 0.0f;
        float z0 = 0.f, z1 = 0.f, lutA = 0.f, lutB = 0.f;
        float cur[8], nxt[8];
        #pragma unroll
        for (int l = 0; l < 8; l++) cur[l] = __ldg(&g_syn[l * SUB + s]);
        float* ringw = sm + RING0 + s * 513;
        const float* lut = sm + LUT0;

        for (int kc = 0; kc < NCH; kc++) {
            __syncthreads();
            int t0 = kc * 8, c0 = t0 & 255;
            const float* hrow = sm + HB0 + (kc & 3) * 136;
            float K[8];
            #pragma unroll
            for (int l = 0; l < 8; l++) K[l] = hrow[l * 17 + s] + cur[l];
            #pragma unroll
            for (int l = 0; l < 8; l++) {
                int tn = t0 + 8 + l;
                nxt[l] = (tn < TD) ? __ldg(&g_syn[tn * SUB + s]) : 0.0f;
            }
            float fb[31];
            #pragma unroll
            for (int i = 0; i < 23; i++) fb[i] = carry[i];
            #pragma unroll
            for (int l = 0; l < 8; l++) {
                float zn = fmaf(twor, z1, fmaf(nr2, z0, lutA));
                z0 = z1; z1 = zn; lutA = lutB;
                float P = 0.0f;
                #pragma unroll
                for (int j = 2; j <= 23; j++)
                    P = fmaf(hkr[j - 1], fb[23 + l - j], P);
                float A = fmaf(hkr[0], fb[22 + l], P);
                float acc = (A + K[l]) + zn;
                bool pr = acc > 0.0f;
                unsigned mm = __ballot_sync(0xffffffffu, pr) & 0xFFFFu;
                float spkf = pr ? 1.0f : 0.0f;
                if (lane < 16) {
                    int c = c0 + l;
                    ringw[c] = spkf; ringw[c + 256] = spkf;
                }
                lutB = lut[(mm & 255u) * 16 + s] + lut[4096 + (mm >> 8) * 16 + s];
                fb[23 + l] = spkf;
            }
            #pragma unroll
            for (int i = 0; i < 23; i++) carry[i] = fb[8 + i];
            #pragma unroll
            for (int l = 0; l < 8; l++) cur[l] = nxt[l];
        }
        __syncthreads();
    } else if (wid == 4) {
        // ------------- output warp: chunk kc-1 as coalesced STG.128 ---------
        int tq = lane >> 2;               // step within chunk
        int s0 = (lane & 3) * 4;
        const float* r0 = sm + RING0 + (s0 + 0) * 513;
        const float* r1 = sm + RING0 + (s0 + 1) * 513;
        const float* r2 = sm + RING0 + (s0 + 2) * 513;
        const float* r3 = sm + RING0 + (s0 + 3) * 513;
        float4* o4 = (float4*)out;
        for (int kc = 0; kc < NCH; kc++) {
            __syncthreads();
            if (kc > 0) {
                int tb = (kc - 1) * 8;
                int c = (tb + tq) & 255;
                float4 v = make_float4(r0[c], r1[c], r2[c], r3[c]);
                o4[tb * 4 + lane] = v;
            }
        }
        __syncthreads();
        {
            int tb = (NCH - 1) * 8;
            int c = (tb + tq) & 255;
            float4 v = make_float4(r0[c], r1[c], r2[c], r3[c]);
            o4[tb * 4 + lane] = v;
        }
    } else if (wid != 12 && wid != 16) {
        // ------------- helpers: hist d = 24..200 for chunk kc+2 -------------
        int s = wid - 1 - (wid > 3) - (wid > 11) - (wid > 15);
        int d0 = 24 + 6 * lane;
        float w[6];
        #pragma unroll
        for (int j = 0; j < 6; j++) {
            int d = d0 + j;
            w[j] = (d <= T_NO) ? g_hk[s * T_NO + d - 1] : 0.0f;
        }
        const float* ringr = sm + RING0 + s * 513;
        float* pw = sm + PART0 + s * 288;
        int lq = lane & 7, q = lane >> 3;

        for (int kc = 0; kc < NCH; kc++) {
            __syncthreads();
            int t1b = kc * 8 + 16;                 // chunk kc+2 start
            int a0 = 256 + (t1b & 255) - d0 - 5;
            float xw[13];
            #pragma unroll
            for (int i = 0; i < 13; i++) xw[i] = ringr[a0 + i];
            float acc[8];
            #pragma unroll
            for (int l = 0; l < 8; l++) acc[l] = 0.0f;
            #pragma unroll
            for (int j = 0; j < 6; j++)
                #pragma unroll
                for (int l = 0; l < 8; l++)
                    acc[l] = fmaf(w[j], xw[5 + l - j], acc[l]);
            #pragma unroll
            for (int l = 0; l < 8; l++) pw[lane * 9 + l] = acc[l];
            __syncwarp();
            float v = 0.0f;
            #pragma unroll
            for (int j = 0; j < 8; j++) v += pw[(8 * q + j) * 9 + lq];
            v += __shfl_xor_sync(0xffffffffu, v, 8);
            v += __shfl_xor_sync(0xffffffffu, v, 16);
            if (lane < 8) sm[HB0 + ((kc + 2) & 3) * 136 + lane * 17 + s] = v;
        }
        __syncthreads();
    } else {
        for (int kc = 0; kc < NCH; kc++) __syncthreads();
        __syncthreads();
    }
}

extern "C" void kernel_launch(void* const* d_in, const int* in_sizes, int n_in,
                              void* d_out, int out_size)
{
    const float* S_e     = (const float*)d_in[0];
    const float* S_i     = (const float*)d_in[1];
    const float* C_den   = (const float*)d_in[2];
    const float* C_syn_e = (const float*)d_in[3];
    const float* C_syn_i = (const float*)d_in[4];
    const float* Tau_e   = (const float*)d_in[5];
    const float* Tau_i   = (const float*)d_in[6];
    const float* W_e     = (const float*)d_in[7];
    const float* W_i     = (const float*)d_in[8];
    const float* D_e     = (const float*)d_in[9];
    const float* D_i     = (const float*)d_in[10];
    const float* Tau_spk = (const float*)d_in[11];
    const float* W_spk   = (const float*)d_in[12];
    const float* W_hist  = (const float*)d_in[13];
    const float* Theta   = (const float*)d_in[14];
    float* out = (float*)d_out;

    cudaFuncSetAttribute(k_scan, cudaFuncAttributeMaxDynamicSharedMemorySize,
                         SMF * 4);
    k_prep<<<1, 256>>>(C_syn_e, C_syn_i, C_den, Tau_e, Tau_i, W_e, W_i,
                       D_e, D_i, Tau_spk, W_spk, W_hist,
                       out + (size_t)TD * SUB);
    k_syn<<<TD, 128>>>(S_e, S_i);
    dim3 cgrid((TD + CT2 - 1) / CT2, SUB);
    k_conv<<<cgrid, 256>>>(Theta);
    k_scan<<<1, 640, SMF * 4>>>(out);
}